// round 9
// baseline (speedup 1.0000x reference)
#include <cuda_runtime.h>

#define TT 512
#define BB 16384
#define HH 32
#define BLK 256
#define LPC 128           // lanes per CTA
#define ASTU 34           // u64 stride per act row (16B-aligned, conflict-free)

typedef unsigned long long u64;

// ---- packed f32x2 helpers (PTX-only; ptxas never auto-fuses) ----
__device__ __forceinline__ u64 fma2(u64 a, u64 b, u64 c) {
    u64 d; asm("fma.rn.f32x2 %0,%1,%2,%3;" : "=l"(d) : "l"(a), "l"(b), "l"(c)); return d;
}
__device__ __forceinline__ u64 mul2(u64 a, u64 b) {
    u64 d; asm("mul.rn.f32x2 %0,%1,%2;" : "=l"(d) : "l"(a), "l"(b)); return d;
}
__device__ __forceinline__ u64 add2(u64 a, u64 b) {
    u64 d; asm("add.rn.f32x2 %0,%1,%2;" : "=l"(d) : "l"(a), "l"(b)); return d;
}
__device__ __forceinline__ u64 pack2(float lo, float hi) {
    u64 r; asm("mov.b64 %0,{%1,%2};" : "=l"(r) : "f"(lo), "f"(hi)); return r;
}
__device__ __forceinline__ u64 dup2(float x) { return pack2(x, x); }
__device__ __forceinline__ void unpack2(u64 v, float& lo, float& hi) {
    asm("mov.b64 {%0,%1},%2;" : "=f"(lo), "=f"(hi) : "l"(v));
}

// stable softplus + sigmoid sharing one exp
__device__ __forceinline__ void sp_sig(float z, float& sp, float& sg) {
    float u = __expf(-fabsf(z));
    float d = 1.0f + u;
    float r = __fdividef(1.0f, d);
    sp = fmaxf(z, 0.0f) + __logf(d);
    sg = (z >= 0.0f) ? r : 1.0f - r;
}
__device__ __forceinline__ float sigf(float z) {
    float u = __expf(-fabsf(z));
    float r = __fdividef(1.0f, 1.0f + u);
    return (z >= 0.0f) ? r : 1.0f - r;
}

__device__ __forceinline__ u64 shfl_xor64(u64 v, int m) {
    return __shfl_xor_sync(0xffffffffu, v, m);
}

__global__ void __launch_bounds__(BLK, 1) rnncell_dup_kernel(
    const float* __restrict__ eps, const float* __restrict__ hs,
    const float* __restrict__ W1,  const float* __restrict__ b1,
    const float* __restrict__ W2,  const float* __restrict__ b2,
    const float* __restrict__ W3,  float* __restrict__ out)
{
    __shared__ __align__(16) float sW2 [HH * HH];   // W2[k][j]
    __shared__ __align__(16) float sW2T[HH * HH];   // W2T[j][k]
    __shared__ __align__(16) u64   sAct[LPC * ASTU];  // dup-packed activations

    const int tid = threadIdx.x;
    for (int i = tid; i < HH * HH; i += BLK) {
        float w = W2[i];
        sW2[i] = w;
        sW2T[(i & 31) * HH + (i >> 5)] = w;
    }
    __syncthreads();

    const int quarter = tid & 3;      // 8-unit / 8-col chunk
    const int grp     = tid >> 2;     // 0..63
    const int co      = quarter * 8;

    const int gbase = blockIdx.x * LPC + 2 * grp;   // 2 adjacent lanes
    u64* __restrict__ arow0 = sAct + (2 * grp) * ASTU;
    u64* __restrict__ arow1 = arow0 + ASTU;

    // scalar weights for L1 / nonlinearity
    float w1a[8], w1b[8], b1v[8], w3v[8];
    #pragma unroll
    for (int j = 0; j < 8; ++j) {
        w1a[j] = W1[co + j];
        w1b[j] = W1[HH + co + j];
        b1v[j] = b1[co + j];
        w3v[j] = W3[co + j];
    }
    // col-pair packed for MV1 init + epilogue dots
    u64 b2pk[4], w1apk[4], w1bpk[4];
    #pragma unroll
    for (int j = 0; j < 4; ++j) {
        b2pk [j] = pack2(b2[co + 2*j], b2[co + 2*j + 1]);
        w1apk[j] = pack2(w1a[2*j], w1a[2*j + 1]);
        w1bpk[j] = pack2(w1b[2*j], w1b[2*j + 1]);
    }

    float gam0 = 0.0f, gam1 = 0.0f;
    float e0, e1, h0, h1;
    {
        float2 ev = *(const float2*)(eps + gbase);
        float2 hv = *(const float2*)(hs  + gbase);
        e0 = ev.x; e1 = ev.y; h0 = hv.x; h1 = hv.y;
    }

    for (int t = 0; t < TT; ++t) {
        const int tn = (t + 1 < TT) ? t + 1 : t;
        float2 en = *(const float2*)(eps + (size_t)tn * BB + gbase);
        float2 hn = *(const float2*)(hs  + (size_t)tn * BB + gbase);

        // ---- layer 1 (scalar, my 8 units x 2 lanes); stage dup-packed softplus
        u64 s1p0[4], s1p1[4];
        {
            u64 ad[8];
            float sg[8];
            #pragma unroll
            for (int u = 0; u < 8; ++u) {
                float z = fmaf(e0, w1a[u], fmaf(gam0, w1b[u], b1v[u]));
                float sp; sp_sig(z, sp, sg[u]);
                ad[u] = dup2(sp);
            }
            #pragma unroll
            for (int j = 0; j < 4; ++j) {
                s1p0[j] = pack2(sg[2*j], sg[2*j + 1]);
                *(ulonglong2*)(arow0 + co + 2*j) = make_ulonglong2(ad[2*j], ad[2*j + 1]);
            }
            #pragma unroll
            for (int u = 0; u < 8; ++u) {
                float z = fmaf(e1, w1a[u], fmaf(gam1, w1b[u], b1v[u]));
                float sp; sp_sig(z, sp, sg[u]);
                ad[u] = dup2(sp);
            }
            #pragma unroll
            for (int j = 0; j < 4; ++j) {
                s1p1[j] = pack2(sg[2*j], sg[2*j + 1]);
                *(ulonglong2*)(arow1 + co + 2*j) = make_ulonglong2(ad[2*j], ad[2*j + 1]);
            }
        }
        __syncwarp();

        // ---- matvec1: z2[my 8 cols] = b2 + sum_k a1[k] * W2[k][.] ----
        u64 acc0[4], acc1[4];
        #pragma unroll
        for (int j = 0; j < 4; ++j) { acc0[j] = b2pk[j]; acc1[j] = b2pk[j]; }

        #pragma unroll
        for (int kp = 0; kp < 16; ++kp) {
            ulonglong2 A0 = *(const ulonglong2*)(arow0 + 2*kp);  // dup a1[2kp],[2kp+1]
            ulonglong2 A1 = *(const ulonglong2*)(arow1 + 2*kp);
            const float* wr0 = sW2 + (2*kp) * HH + co;
            ulonglong2 Wa = *(const ulonglong2*)wr0;        // k even: colpairs 0,1
            ulonglong2 Wb = *(const ulonglong2*)(wr0 + 4);  //         colpairs 2,3
            ulonglong2 Wc = *(const ulonglong2*)(wr0 + HH);      // k odd
            ulonglong2 Wd = *(const ulonglong2*)(wr0 + HH + 4);
            acc0[0] = fma2(A0.x, Wa.x, acc0[0]);
            acc0[1] = fma2(A0.x, Wa.y, acc0[1]);
            acc0[2] = fma2(A0.x, Wb.x, acc0[2]);
            acc0[3] = fma2(A0.x, Wb.y, acc0[3]);
            acc1[0] = fma2(A1.x, Wa.x, acc1[0]);
            acc1[1] = fma2(A1.x, Wa.y, acc1[1]);
            acc1[2] = fma2(A1.x, Wb.x, acc1[2]);
            acc1[3] = fma2(A1.x, Wb.y, acc1[3]);
            acc0[0] = fma2(A0.y, Wc.x, acc0[0]);
            acc0[1] = fma2(A0.y, Wc.y, acc0[1]);
            acc0[2] = fma2(A0.y, Wd.x, acc0[2]);
            acc0[3] = fma2(A0.y, Wd.y, acc0[3]);
            acc1[0] = fma2(A1.y, Wc.x, acc1[0]);
            acc1[1] = fma2(A1.y, Wc.y, acc1[1]);
            acc1[2] = fma2(A1.y, Wd.x, acc1[2]);
            acc1[3] = fma2(A1.y, Wd.y, acc1[3]);
        }
        __syncwarp();

        // ---- v2 = sigmoid(z2) * W3, dup-staged ----
        {
            u64 vd[8];
            #pragma unroll
            for (int j = 0; j < 4; ++j) {
                float za, zb; unpack2(acc0[j], za, zb);
                vd[2*j]   = dup2(sigf(za) * w3v[2*j]);
                vd[2*j+1] = dup2(sigf(zb) * w3v[2*j+1]);
            }
            #pragma unroll
            for (int j = 0; j < 4; ++j)
                *(ulonglong2*)(arow0 + co + 2*j) = make_ulonglong2(vd[2*j], vd[2*j + 1]);
            #pragma unroll
            for (int j = 0; j < 4; ++j) {
                float za, zb; unpack2(acc1[j], za, zb);
                vd[2*j]   = dup2(sigf(za) * w3v[2*j]);
                vd[2*j+1] = dup2(sigf(zb) * w3v[2*j+1]);
            }
            #pragma unroll
            for (int j = 0; j < 4; ++j)
                *(ulonglong2*)(arow1 + co + 2*j) = make_ulonglong2(vd[2*j], vd[2*j + 1]);
        }
        __syncwarp();

        // ---- matvec2: t[my 8 rows] = sum_j v2[j] * W2T[j][.] ----
        u64 tacc0[4], tacc1[4];
        #pragma unroll
        for (int j = 0; j < 4; ++j) { tacc0[j] = 0ull; tacc1[j] = 0ull; }

        #pragma unroll
        for (int kp = 0; kp < 16; ++kp) {
            ulonglong2 A0 = *(const ulonglong2*)(arow0 + 2*kp);
            ulonglong2 A1 = *(const ulonglong2*)(arow1 + 2*kp);
            const float* wr0 = sW2T + (2*kp) * HH + co;
            ulonglong2 Wa = *(const ulonglong2*)wr0;
            ulonglong2 Wb = *(const ulonglong2*)(wr0 + 4);
            ulonglong2 Wc = *(const ulonglong2*)(wr0 + HH);
            ulonglong2 Wd = *(const ulonglong2*)(wr0 + HH + 4);
            tacc0[0] = fma2(A0.x, Wa.x, tacc0[0]);
            tacc0[1] = fma2(A0.x, Wa.y, tacc0[1]);
            tacc0[2] = fma2(A0.x, Wb.x, tacc0[2]);
            tacc0[3] = fma2(A0.x, Wb.y, tacc0[3]);
            tacc1[0] = fma2(A1.x, Wa.x, tacc1[0]);
            tacc1[1] = fma2(A1.x, Wa.y, tacc1[1]);
            tacc1[2] = fma2(A1.x, Wb.x, tacc1[2]);
            tacc1[3] = fma2(A1.x, Wb.y, tacc1[3]);
            tacc0[0] = fma2(A0.y, Wc.x, tacc0[0]);
            tacc0[1] = fma2(A0.y, Wc.y, tacc0[1]);
            tacc0[2] = fma2(A0.y, Wd.x, tacc0[2]);
            tacc0[3] = fma2(A0.y, Wd.y, tacc0[3]);
            tacc1[0] = fma2(A1.y, Wc.x, tacc1[0]);
            tacc1[1] = fma2(A1.y, Wc.y, tacc1[1]);
            tacc1[2] = fma2(A1.y, Wd.x, tacc1[2]);
            tacc1[3] = fma2(A1.y, Wd.y, tacc1[3]);
        }
        __syncwarp();   // MV2 reads done before next iteration's L1 stores

        // ---- epilogue: v1 = sig1 .* t ; dots ; packed 4-thread butterfly ----
        float g00, g10, g01, g11;
        {
            u64 g0p = 0ull, g1p = 0ull;
            #pragma unroll
            for (int j = 0; j < 4; ++j) {
                u64 v1 = mul2(s1p0[j], tacc0[j]);
                g0p = fma2(v1, w1apk[j], g0p);
                g1p = fma2(v1, w1bpk[j], g1p);
            }
            float a, b;
            unpack2(g0p, a, b); g00 = a + b;
            unpack2(g1p, a, b); g10 = a + b;
            g0p = 0ull; g1p = 0ull;
            #pragma unroll
            for (int j = 0; j < 4; ++j) {
                u64 v1 = mul2(s1p1[j], tacc1[j]);
                g0p = fma2(v1, w1apk[j], g0p);
                g1p = fma2(v1, w1bpk[j], g1p);
            }
            unpack2(g0p, a, b); g01 = a + b;
            unpack2(g1p, a, b); g11 = a + b;
        }
        u64 G0 = pack2(g00, g01);
        u64 G1 = pack2(g10, g11);
        G0 = add2(G0, shfl_xor64(G0, 1));
        G0 = add2(G0, shfl_xor64(G0, 2));
        G1 = add2(G1, shfl_xor64(G1, 1));
        G1 = add2(G1, shfl_xor64(G1, 2));

        if (quarter == 0)
            *(u64*)(out + (size_t)t * BB + gbase) = G0;   // two floats

        float g1a, g1b;
        unpack2(G1, g1a, g1b);
        gam0 = fmaf(h0, -g1a, gam0);
        gam1 = fmaf(h1, -g1b, gam1);

        e0 = en.x; e1 = en.y;
        h0 = hn.x; h1 = hn.y;
    }
}

extern "C" void kernel_launch(void* const* d_in, const int* in_sizes, int n_in,
                              void* d_out, int out_size) {
    const float* eps = (const float*)d_in[0];
    const float* hs  = (const float*)d_in[1];
    const float* W1  = (const float*)d_in[2];
    const float* b1  = (const float*)d_in[3];
    const float* W2  = (const float*)d_in[4];
    const float* b2  = (const float*)d_in[5];
    const float* W3  = (const float*)d_in[6];
    float* out = (float*)d_out;

    // 16384 lanes / 128 per CTA = 128 CTAs x 256 threads -> 2 warps/SMSP
    rnncell_dup_kernel<<<BB / LPC, BLK>>>(eps, hs, W1, b1, W2, b2, W3, out);
}